// round 11
// baseline (speedup 1.0000x reference)
#include <cuda_runtime.h>
#include <cuda_bf16.h>

// Problem constants (fixed by the reference)
#define BB      2
#define XX      200
#define YY      200
#define ZZ      16      // == HEIGHT, h = 1
#define CC      17
#define EMPTY_LABEL 16
#define CHOOSE  4000

#define TPB 256
#define COLS_PER_BLK 16
#define BLKS_PER_B (CHOOSE / COLS_PER_BLK)    // 250
#define GRID (BB * BLKS_PER_B)                // 500  (single wave: < 148*8)

// Persistent device scratch (allocation-free).
// g_cnt / g_loss start zero (static init) and are re-zeroed by K3 every call.
// g_bar is a MONOTONIC epoch counter (never reset).
__device__ int                 g_cnt[BB * ZZ];
__device__ float               g_loss[BB];
__device__ unsigned long long  g_bar;

__device__ __forceinline__ void cp16(unsigned smem_addr, const void* gptr) {
    asm volatile("cp.async.cg.shared.global [%0], [%1], 16;"
                 :: "r"(smem_addr), "l"(gptr));
}

// ---------------------------------------------------------------------------
// Fused: counts + barrier + weights + softmax-loss in ONE kernel.
__global__ void __launch_bounds__(TPB)
fused_loss(const float* __restrict__ preds,
           const int*   __restrict__ labels,
           const int*   __restrict__ sel) {
    const int bid = blockIdx.x;
    const int tid = threadIdx.x;
    const int b  = bid / BLKS_PER_B;
    const int cb = bid % BLKS_PER_B;
    const int w    = tid >> 5;
    const int lane = tid & 31;

    __shared__ float s_pred[COLS_PER_BLK * ZZ * CC];   // 17408B
    __shared__ int   s_lab [COLS_PER_BLK * ZZ];        // 1KB
    __shared__ int   s_zcnt[ZZ];
    __shared__ float s_wsum[TPB / 32];
    __shared__ unsigned long long s_target;

    if (tid < ZZ) s_zcnt[tid] = 0;

    // ---- sel for this warp's 2 columns (lanes 0,1), broadcast --------------
    int colv = 0;
    if (lane < 2) {
        int2 xy = __ldg((const int2*)sel + b * CHOOSE + cb * COLS_PER_BLK + 2 * w + lane);
        colv = (b * XX + xy.x) * YY + xy.y;
    }
    const int colA = __shfl_sync(0xffffffffu, colv, 0);
    const int colB = __shfl_sync(0xffffffffu, colv, 1);

    // ---- group 0: labels (needed first, for counts) -------------------------
    if (lane < 8) {
        int c = (lane < 4) ? colA : colB;
        unsigned dl = (unsigned)__cvta_generic_to_shared(
                          s_lab + (2 * w + (lane >> 2)) * ZZ) + (lane & 3) * 16;
        cp16(dl, (const int4*)(labels + (long long)c * ZZ) + (lane & 3));
    }
    asm volatile("cp.async.commit_group;");

    // ---- group 1: preds (2 x 1088B per warp) --------------------------------
    {
        const float4* __restrict__ srcA = (const float4*)preds + (long long)colA * 68;
        const float4* __restrict__ srcB = (const float4*)preds + (long long)colB * 68;
        unsigned dstA = (unsigned)__cvta_generic_to_shared(s_pred + (2 * w)     * (ZZ * CC));
        unsigned dstB = (unsigned)__cvta_generic_to_shared(s_pred + (2 * w + 1) * (ZZ * CC));
        cp16(dstA + lane * 16,        srcA + lane);
        cp16(dstB + lane * 16,        srcB + lane);
        cp16(dstA + (lane + 32) * 16, srcA + lane + 32);
        cp16(dstB + (lane + 32) * 16, srcB + lane + 32);
        if (lane < 4) {
            cp16(dstA + (lane + 64) * 16, srcA + lane + 64);
            cp16(dstB + (lane + 64) * 16, srcB + lane + 64);
        }
        asm volatile("cp.async.commit_group;");
    }

    // ---- wait labels only (preds keep flying); counts -----------------------
    asm volatile("cp.async.wait_group 1;");
    __syncwarp();

    const int z   = lane & 15;
    const int lcl = lane >> 4;
    const int lab = s_lab[(2 * w + lcl) * ZZ + z];
    const bool valid = (lab != EMPTY_LABEL);

    unsigned bal = __ballot_sync(0xffffffffu, valid);
    if (lane < ZZ) {
        int c2 = __popc(bal & ((1u << lane) | (1u << (lane + 16))));
        if (c2) atomicAdd(&s_zcnt[lane], c2);      // shared agg (8 warps)
    }
    __syncthreads();
    if (tid < ZZ) {
        if (s_zcnt[tid]) atomicAdd(&g_cnt[b * ZZ + tid], s_zcnt[tid]);  // RED
    }
    __threadfence();

    // ---- grid barrier (monotonic epoch counter) -----------------------------
    if (tid == 0) {
        unsigned long long old = atomicAdd(&g_bar, 1ULL);
        s_target = (old / GRID + 1ULL) * GRID;
    }
    __syncthreads();
    if (tid == 0) {
        volatile unsigned long long* vb = (volatile unsigned long long*)&g_bar;
        while (*vb < s_target) { __nanosleep(32); }
        __threadfence();   // acquire: all g_cnt REDs visible
    }
    __syncthreads();

    // ---- weights in registers (L2 hits) --------------------------------------
    const int cz = g_cnt[b * ZZ + z];
    int maxc = cz;
    #pragma unroll
    for (int o = 1; o < 16; o <<= 1)
        maxc = max(maxc, __shfl_xor_sync(0xffffffffu, maxc, o));
    const float maxcf = fmaxf((float)maxc, 1.0f);
    const float LOG_RATIO = -1.0986122886681098f;   // ln(1/3)
    const float wz = (cz > 0) ? 3.0f * __expf(((float)cz / maxcf) * LOG_RATIO) : 0.0f;

    // ---- preds have long since landed; softmax + smooth-L1 -------------------
    asm volatile("cp.async.wait_group 0;");
    __syncwarp();

    float val = 0.0f;
    if (valid) {
        const float* __restrict__ p = s_pred + (2 * w + lcl) * (ZZ * CC) + z * CC;
        float s = 0.0f;
        #pragma unroll
        for (int c = 0; c < CC; c++) s += __expf(p[c]);   // conflict-free LDS
        const float plab = __fdividef(__expf(p[lab]), s);
        const float ll = __logf(plab + 0.001f);
        const float wl = wz * ll;
        const float ax = fabsf(wl);
        val = (ax < 1.0f) ? 0.5f * wl * wl : (ax - 0.5f);
    }

    // ---- warp reduce -> smem; one fire-and-forget RED per block --------------
    #pragma unroll
    for (int off = 16; off > 0; off >>= 1)
        val += __shfl_down_sync(0xffffffffu, val, off);
    if (lane == 0) s_wsum[w] = val;
    __syncthreads();

    if (tid == 0) {
        float v = 0.0f;
        #pragma unroll
        for (int i = 0; i < TPB / 32; i++) v += s_wsum[i];
        atomicAdd(&g_loss[b], v);   // RED: non-blocking, no exit convoy
    }
}

// ---------------------------------------------------------------------------
// K3: finalize + reset (one warp; all loads parallel).
__global__ void k3_final(float* __restrict__ out) {
    const int lane = threadIdx.x;
    int c = g_cnt[lane];                     // lanes 0-15: batch0, 16-31: batch1
    float l = (lane < BB) ? g_loss[lane] : 0.0f;

    int n = c;
    #pragma unroll
    for (int o = 1; o < 16; o <<= 1)
        n += __shfl_xor_sync(0xffffffffu, n, o);   // sums within 16-lane halves

    const int   n0 = __shfl_sync(0xffffffffu, n, 0);
    const int   n1 = __shfl_sync(0xffffffffu, n, 16);
    const float l0 = __shfl_sync(0xffffffffu, l, 0);
    const float l1 = __shfl_sync(0xffffffffu, l, 1);

    if (lane == 0) {
        float r0 = l0 / fmaxf((float)n0, 1.0f);
        float r1 = l1 / fmaxf((float)n1, 1.0f);
        out[0] = 0.5f * (r0 + r1);
    }
    // reset for next call (graph replay / re-validation)
    g_cnt[lane] = 0;
    if (lane < BB) g_loss[lane] = 0.0f;
}

extern "C" void kernel_launch(void* const* d_in, const int* in_sizes, int n_in,
                              void* d_out, int out_size) {
    const float* preds  = nullptr;
    const int*   labels = nullptr;
    const int*   sel    = nullptr;
    for (int i = 0; i < n_in; i++) {
        if (in_sizes[i] == BB * XX * YY * ZZ * CC)      preds  = (const float*)d_in[i];
        else if (in_sizes[i] == BB * XX * YY * ZZ)      labels = (const int*)d_in[i];
        else if (in_sizes[i] == BB * CHOOSE * 2)        sel    = (const int*)d_in[i];
    }
    fused_loss<<<GRID, TPB>>>(preds, labels, sel);
    k3_final<<<1, 32>>>((float*)d_out);
}

// round 15
// speedup vs baseline: 1.0089x; 1.0089x over previous
#include <cuda_runtime.h>
#include <cuda_bf16.h>

// Problem constants (fixed by the reference)
#define BB      2
#define XX      200
#define YY      200
#define ZZ      16      // == HEIGHT, h = 1
#define CC      17
#define EMPTY_LABEL 16
#define CHOOSE  4000

#define TPB 256
#define COLS_PER_BLK 16
#define BLKS_PER_B (CHOOSE / COLS_PER_BLK)    // 250
#define GRID (BB * BLKS_PER_B)                // 500  (single wave: < 148*8)

// Persistent device scratch (allocation-free). SINGLE-buffered, exactly as in
// the last passing version: g_cnt / g_loss start zero (static init) and are
// reset by block 0 AFTER the final barrier each call (sole reader resets after
// use; next launch is stream-ordered behind this kernel's completion).
// g_bar / g_bar2 are MONOTONIC epoch counters (never reset).
__device__ int                 g_cnt[BB * ZZ];
__device__ float               g_loss[BB];
__device__ unsigned long long  g_bar;     // barrier 1: counts ready
__device__ unsigned long long  g_bar2;    // barrier 2: loss REDs done

__device__ __forceinline__ void cp16(unsigned smem_addr, const void* gptr) {
    asm volatile("cp.async.cg.shared.global [%0], [%1], 16;"
                 :: "r"(smem_addr), "l"(gptr));
}

// ---------------------------------------------------------------------------
// ONE kernel == R11's fused_loss (passed) + in-kernel finalize tail.
__global__ void __launch_bounds__(TPB)
fused_loss(const float* __restrict__ preds,
           const int*   __restrict__ labels,
           const int*   __restrict__ sel,
           float*       __restrict__ out) {
    const int bid = blockIdx.x;
    const int tid = threadIdx.x;
    const int b  = bid / BLKS_PER_B;
    const int cb = bid % BLKS_PER_B;
    const int w    = tid >> 5;
    const int lane = tid & 31;

    __shared__ float s_pred[COLS_PER_BLK * ZZ * CC];   // 17408B
    __shared__ int   s_lab [COLS_PER_BLK * ZZ];        // 1KB
    __shared__ int   s_zcnt[ZZ];
    __shared__ float s_wsum[TPB / 32];
    __shared__ unsigned long long s_target;

    if (tid < ZZ) s_zcnt[tid] = 0;

    // ---- sel for this warp's 2 columns (lanes 0,1), broadcast --------------
    int colv = 0;
    if (lane < 2) {
        int2 xy = __ldg((const int2*)sel + b * CHOOSE + cb * COLS_PER_BLK + 2 * w + lane);
        colv = (b * XX + xy.x) * YY + xy.y;
    }
    const int colA = __shfl_sync(0xffffffffu, colv, 0);
    const int colB = __shfl_sync(0xffffffffu, colv, 1);

    // ---- group 0: labels (needed first, for counts) -------------------------
    if (lane < 8) {
        int c = (lane < 4) ? colA : colB;
        unsigned dl = (unsigned)__cvta_generic_to_shared(
                          s_lab + (2 * w + (lane >> 2)) * ZZ) + (lane & 3) * 16;
        cp16(dl, (const int4*)(labels + (long long)c * ZZ) + (lane & 3));
    }
    asm volatile("cp.async.commit_group;");

    // ---- group 1: preds (2 x 1088B per warp) --------------------------------
    {
        const float4* __restrict__ srcA = (const float4*)preds + (long long)colA * 68;
        const float4* __restrict__ srcB = (const float4*)preds + (long long)colB * 68;
        unsigned dstA = (unsigned)__cvta_generic_to_shared(s_pred + (2 * w)     * (ZZ * CC));
        unsigned dstB = (unsigned)__cvta_generic_to_shared(s_pred + (2 * w + 1) * (ZZ * CC));
        cp16(dstA + lane * 16,        srcA + lane);
        cp16(dstB + lane * 16,        srcB + lane);
        cp16(dstA + (lane + 32) * 16, srcA + lane + 32);
        cp16(dstB + (lane + 32) * 16, srcB + lane + 32);
        if (lane < 4) {
            cp16(dstA + (lane + 64) * 16, srcA + lane + 64);
            cp16(dstB + (lane + 64) * 16, srcB + lane + 64);
        }
        asm volatile("cp.async.commit_group;");
    }

    // ---- wait labels only (preds keep flying); counts -----------------------
    asm volatile("cp.async.wait_group 1;");
    __syncwarp();

    const int z   = lane & 15;
    const int lcl = lane >> 4;
    const int lab = s_lab[(2 * w + lcl) * ZZ + z];
    const bool valid = (lab != EMPTY_LABEL);

    unsigned bal = __ballot_sync(0xffffffffu, valid);
    if (lane < ZZ) {
        int c2 = __popc(bal & ((1u << lane) | (1u << (lane + 16))));
        if (c2) atomicAdd(&s_zcnt[lane], c2);      // shared agg (8 warps)
    }
    __syncthreads();
    if (tid < ZZ) {
        if (s_zcnt[tid]) atomicAdd(&g_cnt[b * ZZ + tid], s_zcnt[tid]);  // RED (warp 0)
    }
    __threadfence();

    // ---- grid barrier 1 (monotonic epoch counter) ---------------------------
    if (tid == 0) {
        unsigned long long old = atomicAdd(&g_bar, 1ULL);
        s_target = (old / GRID + 1ULL) * GRID;
    }
    __syncthreads();
    if (tid == 0) {
        volatile unsigned long long* vb = (volatile unsigned long long*)&g_bar;
        while (*vb < s_target) { __nanosleep(32); }
        __threadfence();   // acquire: all g_cnt REDs visible
    }
    __syncthreads();

    // ---- weights in registers (L2 hits) --------------------------------------
    const int cz = g_cnt[b * ZZ + z];
    int maxc = cz;
    #pragma unroll
    for (int o = 1; o < 16; o <<= 1)
        maxc = max(maxc, __shfl_xor_sync(0xffffffffu, maxc, o));
    const float maxcf = fmaxf((float)maxc, 1.0f);
    const float LOG_RATIO = -1.0986122886681098f;   // ln(1/3)
    const float wz = (cz > 0) ? 3.0f * __expf(((float)cz / maxcf) * LOG_RATIO) : 0.0f;

    // ---- preds have long since landed; softmax + smooth-L1 -------------------
    asm volatile("cp.async.wait_group 0;");
    __syncwarp();

    float val = 0.0f;
    if (valid) {
        const float* __restrict__ p = s_pred + (2 * w + lcl) * (ZZ * CC) + z * CC;
        float s = 0.0f;
        #pragma unroll
        for (int c = 0; c < CC; c++) s += __expf(p[c]);   // conflict-free LDS
        const float plab = __fdividef(__expf(p[lab]), s);
        const float ll = __logf(plab + 0.001f);
        const float wl = wz * ll;
        const float ax = fabsf(wl);
        val = (ax < 1.0f) ? 0.5f * wl * wl : (ax - 0.5f);
    }

    // ---- warp reduce -> smem --------------------------------------------------
    #pragma unroll
    for (int off = 16; off > 0; off >>= 1)
        val += __shfl_down_sync(0xffffffffu, val, off);
    if (lane == 0) s_wsum[w] = val;
    __syncthreads();

    // ---- tail: RED loss; barrier 2; block 0 finalizes + resets ---------------
    if (tid == 0) {
        float v = 0.0f;
        #pragma unroll
        for (int i = 0; i < TPB / 32; i++) v += s_wsum[i];
        atomicAdd(&g_loss[b], v);       // single-buffer RED (as in R11)
        __threadfence();                // release before arrival

        unsigned long long old2 = atomicAdd(&g_bar2, 1ULL);   // arrival
        if (bid == 0) {
            unsigned long long tgt = (old2 / GRID + 1ULL) * GRID;
            volatile unsigned long long* vb = (volatile unsigned long long*)&g_bar2;
            while (*vb < tgt) { __nanosleep(32); }
            __threadfence();            // acquire: all g_loss REDs visible

            int n0 = 0, n1 = 0;
            #pragma unroll
            for (int z2 = 0; z2 < ZZ; z2++) {
                n0 += g_cnt[z2];
                n1 += g_cnt[ZZ + z2];
            }
            float r0 = g_loss[0] / fmaxf((float)n0, 1.0f);
            float r1 = g_loss[1] / fmaxf((float)n1, 1.0f);
            out[0] = 0.5f * (r0 + r1);  // single writer, once per call

            // reset for next call (all readers done: bar2 passed)
            #pragma unroll
            for (int i = 0; i < BB * ZZ; i++) g_cnt[i] = 0;
            g_loss[0] = 0.0f;
            g_loss[1] = 0.0f;
        }
        // non-zero blocks: fire-and-forget arrival, exit immediately
    }
}

extern "C" void kernel_launch(void* const* d_in, const int* in_sizes, int n_in,
                              void* d_out, int out_size) {
    const float* preds  = nullptr;
    const int*   labels = nullptr;
    const int*   sel    = nullptr;
    for (int i = 0; i < n_in; i++) {
        if (in_sizes[i] == BB * XX * YY * ZZ * CC)      preds  = (const float*)d_in[i];
        else if (in_sizes[i] == BB * XX * YY * ZZ)      labels = (const int*)d_in[i];
        else if (in_sizes[i] == BB * CHOOSE * 2)        sel    = (const int*)d_in[i];
    }
    fused_loss<<<GRID, TPB>>>(preds, labels, sel, (float*)d_out);
}